// round 7
// baseline (speedup 1.0000x reference)
#include <cuda_runtime.h>

#define NN 2048
#define DD 8
#define HH 64
#define KB 128           // histogram buckets
#define NTH 1024

// Per-h F-table: 32 float4 of F edges (128 values) + {F[128]=0, lo, invD, totS}.
__device__ float4 g_F[HH * 33];

// Order-preserving float <-> uint map (for atomicMin/Max on floats)
__device__ __forceinline__ unsigned fenc(float f) {
    unsigned u = __float_as_uint(f);
    return (u & 0x80000000u) ? ~u : (u | 0x80000000u);
}
__device__ __forceinline__ float fdec(unsigned e) {
    return (e & 0x80000000u) ? __uint_as_float(e ^ 0x80000000u)
                             : __uint_as_float(~e);
}

// ---------------------------------------------------------------------------
// k_hist: block = one h. x2 projections -> 128-bin exact histogram ->
// warp-0 register scan -> write 528B F-table to g_F. 3 barriers, no queries.
// ---------------------------------------------------------------------------
__global__ void __launch_bounds__(NTH) k_hist(const float* __restrict__ msg,
                                              const float* __restrict__ W1) {
    const int h = blockIdx.x;
    __shared__ __align__(16) float w[16];
    __shared__ __align__(16) float cnt[KB];
    __shared__ __align__(16) float sum[KB];
    __shared__ unsigned lo_u, hi_u;

    const int t = threadIdx.x;
    const int lane = t & 31;
    const int wid = t >> 5;

    // prefetch msg rows t and t+1024 (hidden behind barrier B0)
    const float4* m0p = reinterpret_cast<const float4*>(msg + t * 8);
    const float4* m1p = reinterpret_cast<const float4*>(msg + (t + NTH) * 8);
    float4 a0 = m0p[0], a1 = m0p[1];
    float4 c0 = m1p[0], c1 = m1p[1];

    if (t < 16) w[t] = W1[h * 16 + t];
    if (t < KB) { cnt[t] = 0.0f; sum[t] = 0.0f; }
    if (t == NTH - 1) { lo_u = 0xFFFFFFFFu; hi_u = 0u; }
    __syncthreads();  // B0

    float x2_0 = a0.x*w[8]+a0.y*w[9]+a0.z*w[10]+a0.w*w[11]
               + a1.x*w[12]+a1.y*w[13]+a1.z*w[14]+a1.w*w[15];
    float x2_1 = c0.x*w[8]+c0.y*w[9]+c0.z*w[10]+c0.w*w[11]
               + c1.x*w[12]+c1.y*w[13]+c1.z*w[14]+c1.w*w[15];

    float mn = fminf(x2_0, x2_1), mx = fmaxf(x2_0, x2_1);
#pragma unroll
    for (int o = 16; o >= 1; o >>= 1) {
        mn = fminf(mn, __shfl_xor_sync(0xffffffffu, mn, o));
        mx = fmaxf(mx, __shfl_xor_sync(0xffffffffu, mx, o));
    }
    if (lane == 0) {
        atomicMin(&lo_u, fenc(mn));
        atomicMax(&hi_u, fenc(mx));
    }
    __syncthreads();  // B1

    const float lo = fdec(lo_u), hi = fdec(hi_u);
    const float range = fmaxf(hi - lo, 1e-30f);
    const float invD = (float)KB / range;
    const float Delta = range / (float)KB;

    int bi0 = (int)fminf(fmaxf((x2_0 - lo) * invD, 0.0f), (float)(KB - 1));
    int bi1 = (int)fminf(fmaxf((x2_1 - lo) * invD, 0.0f), (float)(KB - 1));
    atomicAdd(&cnt[bi0], 1.0f); atomicAdd(&sum[bi0], x2_0);
    atomicAdd(&cnt[bi1], 1.0f); atomicAdd(&sum[bi1], x2_1);
    __syncthreads();  // B2

    if (wid == 0) {
        float4 cc = reinterpret_cast<const float4*>(cnt)[lane];
        float4 ss = reinterpret_cast<const float4*>(sum)[lane];
        float ctot = cc.x + cc.y + cc.z + cc.w;
        float stot = ss.x + ss.y + ss.z + ss.w;
        float cI = ctot, sI = stot;
#pragma unroll
        for (int o = 1; o < 32; o <<= 1) {
            float nc = __shfl_up_sync(0xffffffffu, cI, o);
            float ns = __shfl_up_sync(0xffffffffu, sI, o);
            if (lane >= o) { cI += nc; sI += ns; }
        }
        const float totS = __shfl_sync(0xffffffffu, sI, 31);
        float pc = cI - ctot, ps = sI - stot;  // exclusive prefix of this chunk
        float thr = lo + (float)(4 * lane) * Delta;
        float F0 = (totS - ps) - thr * (2048.0f - pc); pc += cc.x; ps += ss.x; thr += Delta;
        float F1 = (totS - ps) - thr * (2048.0f - pc); pc += cc.y; ps += ss.y; thr += Delta;
        float F2 = (totS - ps) - thr * (2048.0f - pc); pc += cc.z; ps += ss.z; thr += Delta;
        float F3 = (totS - ps) - thr * (2048.0f - pc);
        g_F[h * 33 + lane] = make_float4(F0, F1, F2, F3);
        if (lane == 31) g_F[h * 33 + 32] = make_float4(0.0f, lo, invD, totS);
    }
}

// ---------------------------------------------------------------------------
// k_emit: block b owns output rows [32b, 32b+32). Loads ALL 64 F-tables
// (34 KB, L2 broadcast) + transposed W1 into smem; warp w handles i=32b+w;
// lane handles h = lane and lane+32; O(1) lerp query per (i,h); warp-shuffle
// reduce over h; direct out write. One barrier.
// ---------------------------------------------------------------------------
__global__ void __launch_bounds__(NTH) k_emit(const float* __restrict__ msg,
                                              const float* __restrict__ W1,
                                              const float* __restrict__ b1,
                                              const float* __restrict__ W2,
                                              const float* __restrict__ b2,
                                              float* __restrict__ out) {
    const int bq = blockIdx.x;
    __shared__ __align__(16) float Ft[HH * 132];   // 33.8 KB
    __shared__ __align__(16) float W1t[16 * 64];   // transposed [k][h]
    __shared__ __align__(16) float W2s[DD * HH];
    __shared__ __align__(16) float msgs[32 * 8];
    __shared__ float b1s[HH];
    __shared__ float b2s[DD];

    const int t = threadIdx.x;
    const int lane = t & 31;
    const int wid = t >> 5;

    float4* Ft4 = reinterpret_cast<float4*>(Ft);
    for (int idx = t; idx < HH * 33; idx += NTH) Ft4[idx] = g_F[idx];
    { int hh = t >> 4, k = t & 15; W1t[k * 64 + hh] = W1[t]; }
    if (t < 64) b1s[t] = b1[t];
    if (t >= 64 && t < 64 + DD * HH) W2s[t - 64] = W2[t - 64];
    if (t >= 576 && t < 576 + DD) b2s[t - 576] = b2[t - 576];
    if (t >= 640 && t < 704)
        reinterpret_cast<float4*>(msgs)[t - 640] =
            reinterpret_cast<const float4*>(msg)[bq * 64 + (t - 640)];
    __syncthreads();

    // broadcast this warp's message row
    float m[8];
#pragma unroll
    for (int k = 0; k < 8; k++) m[k] = msgs[wid * 8 + k];

    float acc[DD];
#pragma unroll
    for (int d = 0; d < DD; d++) acc[d] = 0.0f;

#pragma unroll
    for (int r = 0; r < 2; r++) {
        const int h = lane + r * 32;
        float x1 = 0.0f, x2 = 0.0f;
#pragma unroll
        for (int k = 0; k < 8; k++) {
            x1 += m[k] * W1t[k * 64 + h];          // conflict-free: bank = h%32 = lane
            x2 += m[k] * W1t[(k + 8) * 64 + h];
        }
        float a = x1 + b1s[h];
        float thr = -a;
        const float* F = &Ft[h * 132];
        float4 meta = *reinterpret_cast<const float4*>(F + 128);  // {0, lo, invD, totS}
        float u = (thr - meta.y) * meta.z;
        float f;
        if (u < 0.0f) {
            f = meta.w - thr * 2048.0f;            // exact: all elements active
        } else if (u >= (float)KB) {
            f = 0.0f;                               // exact: none active
        } else {
            int bb = (int)u;
            float fr = u - (float)bb;
            float f0 = F[bb], f1 = F[bb + 1];
            f = f0 + fr * (f1 - f0);
        }
        float T = f - fmaxf(a + x2, 0.0f);
#pragma unroll
        for (int d = 0; d < DD; d++) acc[d] += T * W2s[d * 64 + h];
    }

    // warp reduction over 32 lanes (covers all 64 h)
#pragma unroll
    for (int d = 0; d < DD; d++) {
#pragma unroll
        for (int o = 16; o >= 1; o >>= 1)
            acc[d] += __shfl_xor_sync(0xffffffffu, acc[d], o);
    }
    const float inv = 1.0f / (float)(NN - 1);
#pragma unroll
    for (int d = 0; d < DD; d++)
        if (lane == d) out[(bq * 32 + wid) * DD + d] = acc[d] * inv + b2s[d];
}

// ---------------------------------------------------------------------------
extern "C" void kernel_launch(void* const* d_in, const int* in_sizes, int n_in,
                              void* d_out, int out_size) {
    // Identify inputs by element count (all distinct): robust to ordering.
    const float* msg = nullptr;  // 2048*8   = 16384
    const float* W1  = nullptr;  // 64*16    = 1024
    const float* b1  = nullptr;  // 64
    const float* W2  = nullptr;  // 8*64     = 512
    const float* b2  = nullptr;  // 8
    for (int k = 0; k < n_in; k++) {
        switch (in_sizes[k]) {
            case 16384: msg = (const float*)d_in[k]; break;
            case 1024:  W1  = (const float*)d_in[k]; break;
            case 64:    b1  = (const float*)d_in[k]; break;
            case 512:   W2  = (const float*)d_in[k]; break;
            case 8:     b2  = (const float*)d_in[k]; break;
            default: break;
        }
    }
    float* out = (float*)d_out;

    k_hist<<<HH, NTH>>>(msg, W1);
    k_emit<<<HH, NTH>>>(msg, W1, b1, W2, b2, out);
}